// round 11
// baseline (speedup 1.0000x reference)
#include <cuda_runtime.h>
#include <cuda_fp16.h>
#include <cstdint>

#define N_NODES 100000
#define N_EDGES 1600000
#define IN_DIM  256
#define HID     128
#define OUT_DIM 64

#define SCAN_CHUNK 1024
#define N_CHUNKS   ((N_NODES + SCAN_CHUNK - 1) / SCAN_CHUNK)   // 98

// Scratch (static device allocations — no cudaMalloc allowed)
__device__ __half g_h16[(size_t)N_NODES * HID];    // GEMM outputs (fp16)
__device__ __half g_agg16[(size_t)N_NODES * HID];  // aggregation outputs (fp16)
__device__ float  g_dinv[N_NODES];
__device__ int    g_src[N_EDGES];
__device__ int    g_dst[N_EDGES];
__device__ int    g_degi[N_NODES];
__device__ int    g_rowstart[N_NODES];
__device__ int    g_cursor[N_NODES];
__device__ int    g_csr_src[N_EDGES];
__device__ int    g_bsum[N_CHUNKS];
__device__ int    g_is64;

// fp16 transposed weights: Wt[n][k]
__device__ __half g_wt1[HID * IN_DIM];
__device__ __half g_wt2[HID * HID];
__device__ __half g_wtf1[HID * HID];
__device__ __half g_wtf2[OUT_DIM * HID];

// ======================= edge prologue =====================================
__global__ void k_detect(const int* __restrict__ ei32) {
    if (threadIdx.x == 0 && blockIdx.x == 0) {
        int all0 = 1;
        for (int i = 0; i < 256; i++)
            if (ei32[2 * i + 1] != 0) { all0 = 0; break; }
        g_is64 = all0;
    }
}

__global__ void k_zero_deg() {
    int i = blockIdx.x * blockDim.x + threadIdx.x;
    if (i < N_NODES) g_degi[i] = 0;
}

__global__ void k_convert_count(const void* __restrict__ ei) {
    int e = blockIdx.x * blockDim.x + threadIdx.x;
    if (e >= N_EDGES) return;
    int s, d;
    if (g_is64) {
        const long long* p = (const long long*)ei;
        s = (int)p[e];
        d = (int)p[e + N_EDGES];
    } else {
        const int* p = (const int*)ei;
        s = p[e];
        d = p[e + N_EDGES];
    }
    s = min(max(s, 0), N_NODES - 1);
    d = min(max(d, 0), N_NODES - 1);
    g_src[e] = s;
    g_dst[e] = d;
    atomicAdd(&g_degi[d], 1);
}

__global__ void k_scan_sum() {
    __shared__ int sh[SCAN_CHUNK];
    int i = blockIdx.x * SCAN_CHUNK + threadIdx.x;
    sh[threadIdx.x] = (i < N_NODES) ? g_degi[i] : 0;
    __syncthreads();
    for (int off = SCAN_CHUNK / 2; off > 0; off >>= 1) {
        if (threadIdx.x < off) sh[threadIdx.x] += sh[threadIdx.x + off];
        __syncthreads();
    }
    if (threadIdx.x == 0) g_bsum[blockIdx.x] = sh[0];
}

__global__ void k_scan_top() {
    __shared__ int sh[N_CHUNKS];
    if (threadIdx.x < N_CHUNKS) sh[threadIdx.x] = g_bsum[threadIdx.x];
    __syncthreads();
    if (threadIdx.x == 0) {
        int run = 0;
        for (int i = 0; i < N_CHUNKS; i++) { int v = sh[i]; sh[i] = run; run += v; }
    }
    __syncthreads();
    if (threadIdx.x < N_CHUNKS) g_bsum[threadIdx.x] = sh[threadIdx.x];
}

__global__ void k_scan_fin() {
    __shared__ int sh[SCAN_CHUNK];
    int i = blockIdx.x * SCAN_CHUNK + threadIdx.x;
    int v = (i < N_NODES) ? g_degi[i] : 0;
    sh[threadIdx.x] = v;
    __syncthreads();
    for (int off = 1; off < SCAN_CHUNK; off <<= 1) {
        int t = (threadIdx.x >= off) ? sh[threadIdx.x - off] : 0;
        __syncthreads();
        sh[threadIdx.x] += t;
        __syncthreads();
    }
    if (i < N_NODES) {
        int excl = g_bsum[blockIdx.x] + sh[threadIdx.x] - v;
        g_rowstart[i] = excl;
        g_cursor[i]   = excl;
        g_dinv[i]     = rsqrtf(1.0f + (float)g_degi[i]);
    }
}

__global__ void k_bucket() {
    int e = blockIdx.x * blockDim.x + threadIdx.x;
    if (e >= N_EDGES) return;
    int d = g_dst[e];
    int p = atomicAdd(&g_cursor[d], 1);
    g_csr_src[p] = g_src[e];
}

// ================= weight transpose+convert: W[K][N] -> Wt[n][k] fp16 ======
__global__ void k_wt(const float* __restrict__ W, __half* __restrict__ Wt,
                     int K, int N) {
    int idx = blockIdx.x * blockDim.x + threadIdx.x;
    if (idx >= K * N) return;
    int n = idx / K;
    int k = idx - n * K;
    Wt[(size_t)n * K + k] = __float2half(W[(size_t)k * N + n]);
}

// ===================== fp16 mma.sync GEMM (BK=64, 3 CTA/SM) ================
// C[M,BN] = op(A)[M,K] @ W[K,BN], W pre-transposed fp16 Wt[n][k].
// A_HALF: A is fp16 [M,K]; else fp32.
// BM=128, BK=64, 8 warps (4m x 2n), mma.sync.m16n8k16.f16, fp32 accumulate.
// ---------------------------------------------------------------------------
__device__ __forceinline__ void mma_fp16(float d[4], const unsigned a[4], const unsigned b[2]) {
    asm volatile(
        "mma.sync.aligned.m16n8k16.row.col.f32.f16.f16.f32 "
        "{%0,%1,%2,%3}, {%4,%5,%6,%7}, {%8,%9}, {%0,%1,%2,%3};"
        : "+f"(d[0]), "+f"(d[1]), "+f"(d[2]), "+f"(d[3])
        : "r"(a[0]), "r"(a[1]), "r"(a[2]), "r"(a[3]), "r"(b[0]), "r"(b[1]));
}

template <int BN, bool A_HALF, bool PRE, bool EPI_BIAS, bool EPI_RELU, bool HALF_OUT>
__global__ void __launch_bounds__(256, 3)
k_gemm_h(const void* __restrict__ Av, const __half* __restrict__ Wt,
         const float* __restrict__ preB, const float* __restrict__ epiB,
         void* __restrict__ Cv, int M, int K)
{
    constexpr int BM = 128, BK = 64;
    constexpr int WN = BN / 2;
    constexpr int NT = WN / 8;
    constexpr int RS = 36;                  // u32 row stride (32 kpairs + 4 pad)

    __shared__ uint32_t As[BM * RS];
    __shared__ uint32_t Bs[BN * RS];

    const int tid  = threadIdx.x;
    const int wid  = tid >> 5;
    const int lane = tid & 31;
    const int wm   = wid & 3;
    const int wn   = wid >> 2;
    const int bm   = blockIdx.x * BM;
    const int lq   = lane & 3;
    const int lr   = lane >> 2;

    float acc[2][NT][4];
#pragma unroll
    for (int tm = 0; tm < 2; tm++)
#pragma unroll
        for (int tn = 0; tn < NT; tn++)
#pragma unroll
            for (int i = 0; i < 4; i++) acc[tm][tn][i] = 0.0f;

    const __half2 z2 = __floats2half2_rn(0.f, 0.f);

    for (int k0 = 0; k0 < K; k0 += BK) {
        if (A_HALF) {
            // ---- A tile [128 x 64] fp16: 4 uint4 per thread ----
            const __half* Ah = (const __half*)Av;
#pragma unroll
            for (int p = 0; p < 4; p++) {
                int idx = p * 256 + tid;
                int r   = idx >> 3;
                int u   = idx & 7;
                uint4 v = make_uint4(0u, 0u, 0u, 0u);
                if (bm + r < M)
                    v = *(const uint4*)(Ah + (size_t)(bm + r) * K + k0 + u * 8);
                if (PRE) {
                    int c = k0 + u * 8;
                    uint32_t* w = (uint32_t*)&v;
#pragma unroll
                    for (int j = 0; j < 4; j++) {
                        __half2 hb = __floats2half2_rn(preB[c + j * 2], preB[c + j * 2 + 1]);
                        __half2 ha = *(__half2*)&w[j];
                        ha = __hmax2(__hadd2(ha, hb), z2);
                        w[j] = *(uint32_t*)&ha;
                    }
                }
                *(uint4*)&As[r * RS + u * 4] = v;
            }
        } else {
            // ---- A tile [128 x 64] fp32 -> fp16: 2 waves of 4 float4 ----
            const float* Af = (const float*)Av;
#pragma unroll
            for (int ph = 0; ph < 2; ph++) {
                float4 st[4];
#pragma unroll
                for (int p = 0; p < 4; p++) {
                    int idx = (ph * 4 + p) * 256 + tid;
                    int r   = idx >> 4;
                    int f4  = idx & 15;
                    st[p] = make_float4(0.f, 0.f, 0.f, 0.f);
                    if (bm + r < M)
                        st[p] = *(const float4*)&Af[(size_t)(bm + r) * K + k0 + f4 * 4];
                }
#pragma unroll
                for (int p = 0; p < 4; p++) {
                    int idx = (ph * 4 + p) * 256 + tid;
                    int r   = idx >> 4;
                    int f4  = idx & 15;
                    float4 v = st[p];
                    if (PRE) {
                        v.x = fmaxf(v.x + preB[k0 + f4 * 4 + 0], 0.f);
                        v.y = fmaxf(v.y + preB[k0 + f4 * 4 + 1], 0.f);
                        v.z = fmaxf(v.z + preB[k0 + f4 * 4 + 2], 0.f);
                        v.w = fmaxf(v.w + preB[k0 + f4 * 4 + 3], 0.f);
                    }
                    __half2 h01 = __floats2half2_rn(v.x, v.y);
                    __half2 h23 = __floats2half2_rn(v.z, v.w);
                    As[r * RS + f4 * 2]     = *(uint32_t*)&h01;
                    As[r * RS + f4 * 2 + 1] = *(uint32_t*)&h23;
                }
            }
        }
        // ---- B tile: Wt[n][k0..k0+63] fp16 (coalesced uint4, 8/row) ----
        constexpr int BU = BN * 8;
#pragma unroll
        for (int p = 0; p < BU / 256; p++) {
            int idx = p * 256 + tid;
            int n   = idx >> 3;
            int u   = idx & 7;
            uint4 v = *(const uint4*)(Wt + (size_t)n * K + k0 + u * 8);
            *(uint4*)&Bs[n * RS + u * 4] = v;
        }
        __syncthreads();

        // ---- 4 k-steps of 16 ----
#pragma unroll
        for (int ks = 0; ks < 4; ks++) {
            const int kp = ks * 8;
            unsigned af[2][4];
            unsigned bf[NT][2];
#pragma unroll
            for (int tm = 0; tm < 2; tm++) {
                int r = wm * 32 + tm * 16 + lr;
                af[tm][0] = As[r * RS + kp + lq];
                af[tm][1] = As[(r + 8) * RS + kp + lq];
                af[tm][2] = As[r * RS + kp + lq + 4];
                af[tm][3] = As[(r + 8) * RS + kp + lq + 4];
            }
#pragma unroll
            for (int tn = 0; tn < NT; tn++) {
                int c = wn * WN + tn * 8 + lr;
                bf[tn][0] = Bs[c * RS + kp + lq];
                bf[tn][1] = Bs[c * RS + kp + lq + 4];
            }
#pragma unroll
            for (int tm = 0; tm < 2; tm++)
#pragma unroll
                for (int tn = 0; tn < NT; tn++)
                    mma_fp16(acc[tm][tn], af[tm], bf[tn]);
        }
        __syncthreads();
    }

    // ---- epilogue ----
#pragma unroll
    for (int tm = 0; tm < 2; tm++) {
        int r0 = bm + wm * 32 + tm * 16 + lr;
#pragma unroll
        for (int half = 0; half < 2; half++) {
            int r = r0 + half * 8;
            if (r >= M) continue;
#pragma unroll
            for (int tn = 0; tn < NT; tn++) {
                int c = wn * WN + tn * 8 + lq * 2;
                float v0 = acc[tm][tn][half * 2 + 0];
                float v1 = acc[tm][tn][half * 2 + 1];
                if (EPI_BIAS) { v0 += epiB[c]; v1 += epiB[c + 1]; }
                if (EPI_RELU) { v0 = fmaxf(v0, 0.f); v1 = fmaxf(v1, 0.f); }
                if (HALF_OUT) {
                    __half2 hv = __floats2half2_rn(v0, v1);
                    *(__half2*)((__half*)Cv + (size_t)r * BN + c) = hv;
                } else {
                    float* C = (float*)Cv;
                    C[(size_t)r * BN + c]     = v0;
                    C[(size_t)r * BN + c + 1] = v1;
                }
            }
        }
    }
}

// ================ gather aggregation: fp16 in, fp16 out ====================
__device__ __forceinline__ void h16_load4(const __half* base, size_t row,
                                          int lane, float f[4]) {
    uint2 u = *(const uint2*)(base + row * HID + lane * 4);
    __half2 p0 = *(__half2*)&u.x;
    __half2 p1 = *(__half2*)&u.y;
    float2 a = __half22float2(p0);
    float2 b = __half22float2(p1);
    f[0] = a.x; f[1] = a.y; f[2] = b.x; f[3] = b.y;
}

__global__ void __launch_bounds__(256)
k_aggregate(const int* __restrict__ csr_src,
            const int* __restrict__ rowstart,
            const int* __restrict__ degi,
            const __half* __restrict__ h16,
            const float* __restrict__ dinv,
            __half* __restrict__ agg16)
{
    int n    = (blockIdx.x * blockDim.x + threadIdx.x) >> 5;
    int lane = threadIdx.x & 31;
    if (n >= N_NODES) return;

    float di = dinv[n];
    float f[4];
    h16_load4(h16, (size_t)n, lane, f);
    float s0 = di * di;
    float4 acc = make_float4(f[0] * s0, f[1] * s0, f[2] * s0, f[3] * s0);

    int beg = rowstart[n];
    int cnt = degi[n];
    int j = 0;
    for (; j + 2 <= cnt; j += 2) {
        int sa = csr_src[beg + j];
        int sb = csr_src[beg + j + 1];
        float na = dinv[sa] * di;
        float nb = dinv[sb] * di;
        float fa[4], fb[4];
        h16_load4(h16, (size_t)sa, lane, fa);
        h16_load4(h16, (size_t)sb, lane, fb);
        acc.x = fmaf(fa[0], na, acc.x); acc.y = fmaf(fa[1], na, acc.y);
        acc.z = fmaf(fa[2], na, acc.z); acc.w = fmaf(fa[3], na, acc.w);
        acc.x = fmaf(fb[0], nb, acc.x); acc.y = fmaf(fb[1], nb, acc.y);
        acc.z = fmaf(fb[2], nb, acc.z); acc.w = fmaf(fb[3], nb, acc.w);
    }
    if (j < cnt) {
        int sa = csr_src[beg + j];
        float na = dinv[sa] * di;
        float fa[4];
        h16_load4(h16, (size_t)sa, lane, fa);
        acc.x = fmaf(fa[0], na, acc.x); acc.y = fmaf(fa[1], na, acc.y);
        acc.z = fmaf(fa[2], na, acc.z); acc.w = fmaf(fa[3], na, acc.w);
    }
    __half2 o0 = __floats2half2_rn(acc.x, acc.y);
    __half2 o1 = __floats2half2_rn(acc.z, acc.w);
    uint2 u;
    u.x = *(uint32_t*)&o0;
    u.y = *(uint32_t*)&o1;
    *(uint2*)(agg16 + (size_t)n * HID + lane * 4) = u;
}

// ---------------------------------------------------------------------------
extern "C" void kernel_launch(void* const* d_in, const int* in_sizes, int n_in,
                              void* d_out, int out_size)
{
    const float* x   = (const float*)d_in[0];
    const void*  ei  = d_in[1];
    const float* W1  = (const float*)d_in[2];
    const float* b1  = (const float*)d_in[3];
    const float* W2  = (const float*)d_in[4];
    const float* b2  = (const float*)d_in[5];
    const float* Wf1 = (const float*)d_in[6];
    const float* bf1 = (const float*)d_in[7];
    const float* Wf2 = (const float*)d_in[8];
    const float* bf2 = (const float*)d_in[9];
    float* out = (float*)d_out;

    float *dinv;
    __half *h16, *agg16, *wt1, *wt2, *wtf1, *wtf2;
    int *csr_src, *rowstart, *degi;
    cudaGetSymbolAddress((void**)&h16,      g_h16);
    cudaGetSymbolAddress((void**)&agg16,    g_agg16);
    cudaGetSymbolAddress((void**)&dinv,     g_dinv);
    cudaGetSymbolAddress((void**)&csr_src,  g_csr_src);
    cudaGetSymbolAddress((void**)&rowstart, g_rowstart);
    cudaGetSymbolAddress((void**)&degi,     g_degi);
    cudaGetSymbolAddress((void**)&wt1,      g_wt1);
    cudaGetSymbolAddress((void**)&wt2,      g_wt2);
    cudaGetSymbolAddress((void**)&wtf1,     g_wtf1);
    cudaGetSymbolAddress((void**)&wtf2,     g_wtf2);

    static cudaStream_t s2 = nullptr;
    static cudaEvent_t evFork = nullptr, evJoin = nullptr;
    if (!s2) {
        cudaStreamCreateWithFlags(&s2, cudaStreamNonBlocking);
        cudaEventCreateWithFlags(&evFork, cudaEventDisableTiming);
        cudaEventCreateWithFlags(&evJoin, cudaEventDisableTiming);
    }

    const int gm = (N_NODES + 127) / 128;
    const int agg_blocks = (N_NODES * 32 + 255) / 256;

    // --- fork ---
    cudaEventRecord(evFork, 0);
    cudaStreamWaitEvent(s2, evFork, 0);

    // Keep GEMM1 at kernel-launch index 3 (ncu -s 5 lands there).
    k_detect<<<1, 32, 0, s2>>>((const int*)ei);                      // 0
    k_zero_deg<<<(N_NODES + 255) / 256, 256, 0, s2>>>();             // 1
    k_wt<<<(IN_DIM * HID + 255) / 256, 256>>>(W1, wt1, IN_DIM, HID); // 2 (s0)

    // --- GEMM1 (A fp32 = X) on stream 0, fp16 output ---             3 (s0)
    k_gemm_h<HID, false, false, false, false, true><<<gm, 256>>>(
        x, wt1, nullptr, nullptr, h16, N_NODES, IN_DIM);

    // --- rest of CSR prologue + weight converts on s2 ---
    k_convert_count<<<(N_EDGES + 255) / 256, 256, 0, s2>>>(ei);
    k_scan_sum<<<N_CHUNKS, SCAN_CHUNK, 0, s2>>>();
    k_scan_top<<<1, SCAN_CHUNK, 0, s2>>>();
    k_scan_fin<<<N_CHUNKS, SCAN_CHUNK, 0, s2>>>();
    k_bucket<<<(N_EDGES + 255) / 256, 256, 0, s2>>>();
    k_wt<<<(HID * HID + 255) / 256, 256, 0, s2>>>(W2,  wt2,  HID, HID);
    k_wt<<<(HID * HID + 255) / 256, 256, 0, s2>>>(Wf1, wtf1, HID, HID);
    k_wt<<<(HID * OUT_DIM + 255) / 256, 256, 0, s2>>>(Wf2, wtf2, HID, OUT_DIM);
    cudaEventRecord(evJoin, s2);

    // --- join: aggregation needs CSR (s2) + h16 (s0) ---
    cudaStreamWaitEvent(0, evJoin, 0);
    k_aggregate<<<agg_blocks, 256>>>(csr_src, rowstart, degi, h16, dinv, agg16);

    // --- layer 2: A = agg16 (fp16), PRE relu(a+b1) ---
    k_gemm_h<HID, true, true, false, false, true><<<gm, 256>>>(
        agg16, wt2, b1, nullptr, h16, N_NODES, HID);
    k_aggregate<<<agg_blocks, 256>>>(csr_src, rowstart, degi, h16, dinv, agg16);

    // --- MLP head: GEMM3 fp16 out, GEMM4 fp32 out ---
    k_gemm_h<HID, true, true, true, true, true><<<gm, 256>>>(
        agg16, wtf1, b2, bf1, h16, N_NODES, HID);
    k_gemm_h<OUT_DIM, true, false, true, false, false><<<gm, 256>>>(
        h16, wtf2, nullptr, bf2, out, N_NODES, HID);
}

// round 12
// speedup vs baseline: 1.1817x; 1.1817x over previous
#include <cuda_runtime.h>
#include <cuda_fp16.h>
#include <cstdint>

#define N_NODES 100000
#define N_EDGES 1600000
#define IN_DIM  256
#define HID     128
#define OUT_DIM 64

#define SCAN_CHUNK 1024
#define N_CHUNKS   ((N_NODES + SCAN_CHUNK - 1) / SCAN_CHUNK)   // 98

// Scratch (static device allocations — no cudaMalloc allowed)
__device__ __half g_h16[(size_t)N_NODES * HID];    // GEMM outputs (fp16)
__device__ __half g_agg16[(size_t)N_NODES * HID];  // aggregation outputs (fp16)
__device__ float  g_dinv[N_NODES];
__device__ int    g_src[N_EDGES];
__device__ int    g_dst[N_EDGES];
__device__ int    g_degi[N_NODES];
__device__ int    g_rowstart[N_NODES];
__device__ int    g_cursor[N_NODES];
__device__ int    g_csr_src[N_EDGES];
__device__ int    g_bsum[N_CHUNKS];
__device__ int    g_is64;

// fp16 transposed weights: Wt[n][k]
__device__ __half g_wt1[HID * IN_DIM];
__device__ __half g_wt2[HID * HID];
__device__ __half g_wtf1[HID * HID];
__device__ __half g_wtf2[OUT_DIM * HID];

// ======================= edge prologue =====================================
__global__ void k_detect(const int* __restrict__ ei32) {
    if (threadIdx.x == 0 && blockIdx.x == 0) {
        int all0 = 1;
        for (int i = 0; i < 256; i++)
            if (ei32[2 * i + 1] != 0) { all0 = 0; break; }
        g_is64 = all0;
    }
}

__global__ void k_zero_deg() {
    int i = blockIdx.x * blockDim.x + threadIdx.x;
    if (i < N_NODES) g_degi[i] = 0;
}

__global__ void k_convert_count(const void* __restrict__ ei) {
    int e = blockIdx.x * blockDim.x + threadIdx.x;
    if (e >= N_EDGES) return;
    int s, d;
    if (g_is64) {
        const long long* p = (const long long*)ei;
        s = (int)p[e];
        d = (int)p[e + N_EDGES];
    } else {
        const int* p = (const int*)ei;
        s = p[e];
        d = p[e + N_EDGES];
    }
    s = min(max(s, 0), N_NODES - 1);
    d = min(max(d, 0), N_NODES - 1);
    g_src[e] = s;
    g_dst[e] = d;
    atomicAdd(&g_degi[d], 1);
}

__global__ void k_scan_sum() {
    __shared__ int sh[SCAN_CHUNK];
    int i = blockIdx.x * SCAN_CHUNK + threadIdx.x;
    sh[threadIdx.x] = (i < N_NODES) ? g_degi[i] : 0;
    __syncthreads();
    for (int off = SCAN_CHUNK / 2; off > 0; off >>= 1) {
        if (threadIdx.x < off) sh[threadIdx.x] += sh[threadIdx.x + off];
        __syncthreads();
    }
    if (threadIdx.x == 0) g_bsum[blockIdx.x] = sh[0];
}

__global__ void k_scan_top() {
    __shared__ int sh[N_CHUNKS];
    if (threadIdx.x < N_CHUNKS) sh[threadIdx.x] = g_bsum[threadIdx.x];
    __syncthreads();
    if (threadIdx.x == 0) {
        int run = 0;
        for (int i = 0; i < N_CHUNKS; i++) { int v = sh[i]; sh[i] = run; run += v; }
    }
    __syncthreads();
    if (threadIdx.x < N_CHUNKS) g_bsum[threadIdx.x] = sh[threadIdx.x];
}

__global__ void k_scan_fin() {
    __shared__ int sh[SCAN_CHUNK];
    int i = blockIdx.x * SCAN_CHUNK + threadIdx.x;
    int v = (i < N_NODES) ? g_degi[i] : 0;
    sh[threadIdx.x] = v;
    __syncthreads();
    for (int off = 1; off < SCAN_CHUNK; off <<= 1) {
        int t = (threadIdx.x >= off) ? sh[threadIdx.x - off] : 0;
        __syncthreads();
        sh[threadIdx.x] += t;
        __syncthreads();
    }
    if (i < N_NODES) {
        int excl = g_bsum[blockIdx.x] + sh[threadIdx.x] - v;
        g_rowstart[i] = excl;
        g_cursor[i]   = excl;
        g_dinv[i]     = rsqrtf(1.0f + (float)g_degi[i]);
    }
}

__global__ void k_bucket() {
    int e = blockIdx.x * blockDim.x + threadIdx.x;
    if (e >= N_EDGES) return;
    int d = g_dst[e];
    int p = atomicAdd(&g_cursor[d], 1);
    g_csr_src[p] = g_src[e];
}

// ================= weight transpose+convert: W[K][N] -> Wt[n][k] fp16 ======
__global__ void k_wt(const float* __restrict__ W, __half* __restrict__ Wt,
                     int K, int N) {
    int idx = blockIdx.x * blockDim.x + threadIdx.x;
    if (idx >= K * N) return;
    int n = idx / K;
    int k = idx - n * K;
    Wt[(size_t)n * K + k] = __float2half(W[(size_t)k * N + n]);
}

// ===================== fp16 mma.sync GEMM (BK=64) ==========================
// C[M,BN] = op(A)[M,K] @ W[K,BN], W pre-transposed fp16 Wt[n][k].
// A_HALF: A is fp16 [M,K]; else fp32 (single-pass 8x load-cvt-store: ptxas
// front-batches the LDGs -> high per-thread MLP; no occupancy cap — R11
// showed reg-capping this kernel trades MLP for occupancy at a net loss).
// BM=128, BK=64, 8 warps (4m x 2n), mma.sync.m16n8k16.f16, fp32 accumulate.
// ---------------------------------------------------------------------------
__device__ __forceinline__ void mma_fp16(float d[4], const unsigned a[4], const unsigned b[2]) {
    asm volatile(
        "mma.sync.aligned.m16n8k16.row.col.f32.f16.f16.f32 "
        "{%0,%1,%2,%3}, {%4,%5,%6,%7}, {%8,%9}, {%0,%1,%2,%3};"
        : "+f"(d[0]), "+f"(d[1]), "+f"(d[2]), "+f"(d[3])
        : "r"(a[0]), "r"(a[1]), "r"(a[2]), "r"(a[3]), "r"(b[0]), "r"(b[1]));
}

template <int BN, bool A_HALF, bool PRE, bool EPI_BIAS, bool EPI_RELU, bool HALF_OUT>
__global__ void __launch_bounds__(256)
k_gemm_h(const void* __restrict__ Av, const __half* __restrict__ Wt,
         const float* __restrict__ preB, const float* __restrict__ epiB,
         void* __restrict__ Cv, int M, int K)
{
    constexpr int BM = 128, BK = 64;
    constexpr int WN = BN / 2;
    constexpr int NT = WN / 8;
    constexpr int RS = 36;                  // u32 row stride (32 kpairs + 4 pad)

    __shared__ uint32_t As[BM * RS];
    __shared__ uint32_t Bs[BN * RS];

    const int tid  = threadIdx.x;
    const int wid  = tid >> 5;
    const int lane = tid & 31;
    const int wm   = wid & 3;
    const int wn   = wid >> 2;
    const int bm   = blockIdx.x * BM;
    const int lq   = lane & 3;
    const int lr   = lane >> 2;

    float acc[2][NT][4];
#pragma unroll
    for (int tm = 0; tm < 2; tm++)
#pragma unroll
        for (int tn = 0; tn < NT; tn++)
#pragma unroll
            for (int i = 0; i < 4; i++) acc[tm][tn][i] = 0.0f;

    const __half2 z2 = __floats2half2_rn(0.f, 0.f);

    for (int k0 = 0; k0 < K; k0 += BK) {
        if (A_HALF) {
            // ---- A tile [128 x 64] fp16: 4 uint4 per thread ----
            const __half* Ah = (const __half*)Av;
#pragma unroll
            for (int p = 0; p < 4; p++) {
                int idx = p * 256 + tid;
                int r   = idx >> 3;
                int u   = idx & 7;
                uint4 v = make_uint4(0u, 0u, 0u, 0u);
                if (bm + r < M)
                    v = *(const uint4*)(Ah + (size_t)(bm + r) * K + k0 + u * 8);
                if (PRE) {
                    int c = k0 + u * 8;
                    uint32_t* w = (uint32_t*)&v;
#pragma unroll
                    for (int j = 0; j < 4; j++) {
                        __half2 hb = __floats2half2_rn(preB[c + j * 2], preB[c + j * 2 + 1]);
                        __half2 ha = *(__half2*)&w[j];
                        ha = __hmax2(__hadd2(ha, hb), z2);
                        w[j] = *(uint32_t*)&ha;
                    }
                }
                *(uint4*)&As[r * RS + u * 4] = v;
            }
        } else {
            // ---- A tile [128 x 64] fp32 -> fp16: single-pass 8 x float4 ----
            const float* Af = (const float*)Av;
#pragma unroll
            for (int p = 0; p < 8; p++) {
                int idx = p * 256 + tid;
                int r   = idx >> 4;
                int f4  = idx & 15;
                float4 v = make_float4(0.f, 0.f, 0.f, 0.f);
                if (bm + r < M)
                    v = *(const float4*)&Af[(size_t)(bm + r) * K + k0 + f4 * 4];
                if (PRE) {
                    v.x = fmaxf(v.x + preB[k0 + f4 * 4 + 0], 0.f);
                    v.y = fmaxf(v.y + preB[k0 + f4 * 4 + 1], 0.f);
                    v.z = fmaxf(v.z + preB[k0 + f4 * 4 + 2], 0.f);
                    v.w = fmaxf(v.w + preB[k0 + f4 * 4 + 3], 0.f);
                }
                __half2 h01 = __floats2half2_rn(v.x, v.y);
                __half2 h23 = __floats2half2_rn(v.z, v.w);
                As[r * RS + f4 * 2]     = *(uint32_t*)&h01;
                As[r * RS + f4 * 2 + 1] = *(uint32_t*)&h23;
            }
        }
        // ---- B tile: Wt[n][k0..k0+63] fp16 (coalesced uint4, 8/row) ----
        constexpr int BU = BN * 8;
#pragma unroll
        for (int p = 0; p < BU / 256; p++) {
            int idx = p * 256 + tid;
            int n   = idx >> 3;
            int u   = idx & 7;
            uint4 v = *(const uint4*)(Wt + (size_t)n * K + k0 + u * 8);
            *(uint4*)&Bs[n * RS + u * 4] = v;
        }
        __syncthreads();

        // ---- 4 k-steps of 16 ----
#pragma unroll
        for (int ks = 0; ks < 4; ks++) {
            const int kp = ks * 8;
            unsigned af[2][4];
            unsigned bf[NT][2];
#pragma unroll
            for (int tm = 0; tm < 2; tm++) {
                int r = wm * 32 + tm * 16 + lr;
                af[tm][0] = As[r * RS + kp + lq];
                af[tm][1] = As[(r + 8) * RS + kp + lq];
                af[tm][2] = As[r * RS + kp + lq + 4];
                af[tm][3] = As[(r + 8) * RS + kp + lq + 4];
            }
#pragma unroll
            for (int tn = 0; tn < NT; tn++) {
                int c = wn * WN + tn * 8 + lr;
                bf[tn][0] = Bs[c * RS + kp + lq];
                bf[tn][1] = Bs[c * RS + kp + lq + 4];
            }
#pragma unroll
            for (int tm = 0; tm < 2; tm++)
#pragma unroll
                for (int tn = 0; tn < NT; tn++)
                    mma_fp16(acc[tm][tn], af[tm], bf[tn]);
        }
        __syncthreads();
    }

    // ---- epilogue ----
#pragma unroll
    for (int tm = 0; tm < 2; tm++) {
        int r0 = bm + wm * 32 + tm * 16 + lr;
#pragma unroll
        for (int half = 0; half < 2; half++) {
            int r = r0 + half * 8;
            if (r >= M) continue;
#pragma unroll
            for (int tn = 0; tn < NT; tn++) {
                int c = wn * WN + tn * 8 + lq * 2;
                float v0 = acc[tm][tn][half * 2 + 0];
                float v1 = acc[tm][tn][half * 2 + 1];
                if (EPI_BIAS) { v0 += epiB[c]; v1 += epiB[c + 1]; }
                if (EPI_RELU) { v0 = fmaxf(v0, 0.f); v1 = fmaxf(v1, 0.f); }
                if (HALF_OUT) {
                    __half2 hv = __floats2half2_rn(v0, v1);
                    *(__half2*)((__half*)Cv + (size_t)r * BN + c) = hv;
                } else {
                    float* C = (float*)Cv;
                    C[(size_t)r * BN + c]     = v0;
                    C[(size_t)r * BN + c + 1] = v1;
                }
            }
        }
    }
}

// ================ gather aggregation: fp16 in, fp16 out ====================
__device__ __forceinline__ void h16_load4(const __half* base, size_t row,
                                          int lane, float f[4]) {
    uint2 u = *(const uint2*)(base + row * HID + lane * 4);
    __half2 p0 = *(__half2*)&u.x;
    __half2 p1 = *(__half2*)&u.y;
    float2 a = __half22float2(p0);
    float2 b = __half22float2(p1);
    f[0] = a.x; f[1] = a.y; f[2] = b.x; f[3] = b.y;
}

__global__ void __launch_bounds__(256)
k_aggregate(const int* __restrict__ csr_src,
            const int* __restrict__ rowstart,
            const int* __restrict__ degi,
            const __half* __restrict__ h16,
            const float* __restrict__ dinv,
            __half* __restrict__ agg16)
{
    int n    = (blockIdx.x * blockDim.x + threadIdx.x) >> 5;
    int lane = threadIdx.x & 31;
    if (n >= N_NODES) return;

    float di = dinv[n];
    float f[4];
    h16_load4(h16, (size_t)n, lane, f);
    float s0 = di * di;
    float4 acc = make_float4(f[0] * s0, f[1] * s0, f[2] * s0, f[3] * s0);

    int beg = rowstart[n];
    int cnt = degi[n];
    int j = 0;
    for (; j + 2 <= cnt; j += 2) {
        int sa = csr_src[beg + j];
        int sb = csr_src[beg + j + 1];
        float na = dinv[sa] * di;
        float nb = dinv[sb] * di;
        float fa[4], fb[4];
        h16_load4(h16, (size_t)sa, lane, fa);
        h16_load4(h16, (size_t)sb, lane, fb);
        acc.x = fmaf(fa[0], na, acc.x); acc.y = fmaf(fa[1], na, acc.y);
        acc.z = fmaf(fa[2], na, acc.z); acc.w = fmaf(fa[3], na, acc.w);
        acc.x = fmaf(fb[0], nb, acc.x); acc.y = fmaf(fb[1], nb, acc.y);
        acc.z = fmaf(fb[2], nb, acc.z); acc.w = fmaf(fb[3], nb, acc.w);
    }
    if (j < cnt) {
        int sa = csr_src[beg + j];
        float na = dinv[sa] * di;
        float fa[4];
        h16_load4(h16, (size_t)sa, lane, fa);
        acc.x = fmaf(fa[0], na, acc.x); acc.y = fmaf(fa[1], na, acc.y);
        acc.z = fmaf(fa[2], na, acc.z); acc.w = fmaf(fa[3], na, acc.w);
    }
    __half2 o0 = __floats2half2_rn(acc.x, acc.y);
    __half2 o1 = __floats2half2_rn(acc.z, acc.w);
    uint2 u;
    u.x = *(uint32_t*)&o0;
    u.y = *(uint32_t*)&o1;
    *(uint2*)(agg16 + (size_t)n * HID + lane * 4) = u;
}

// ---------------------------------------------------------------------------
extern "C" void kernel_launch(void* const* d_in, const int* in_sizes, int n_in,
                              void* d_out, int out_size)
{
    const float* x   = (const float*)d_in[0];
    const void*  ei  = d_in[1];
    const float* W1  = (const float*)d_in[2];
    const float* b1  = (const float*)d_in[3];
    const float* W2  = (const float*)d_in[4];
    const float* b2  = (const float*)d_in[5];
    const float* Wf1 = (const float*)d_in[6];
    const float* bf1 = (const float*)d_in[7];
    const float* Wf2 = (const float*)d_in[8];
    const float* bf2 = (const float*)d_in[9];
    float* out = (float*)d_out;

    float *dinv;
    __half *h16, *agg16, *wt1, *wt2, *wtf1, *wtf2;
    int *csr_src, *rowstart, *degi;
    cudaGetSymbolAddress((void**)&h16,      g_h16);
    cudaGetSymbolAddress((void**)&agg16,    g_agg16);
    cudaGetSymbolAddress((void**)&dinv,     g_dinv);
    cudaGetSymbolAddress((void**)&csr_src,  g_csr_src);
    cudaGetSymbolAddress((void**)&rowstart, g_rowstart);
    cudaGetSymbolAddress((void**)&degi,     g_degi);
    cudaGetSymbolAddress((void**)&wt1,      g_wt1);
    cudaGetSymbolAddress((void**)&wt2,      g_wt2);
    cudaGetSymbolAddress((void**)&wtf1,     g_wtf1);
    cudaGetSymbolAddress((void**)&wtf2,     g_wtf2);

    static cudaStream_t s2 = nullptr;
    static cudaEvent_t evFork = nullptr, evJoin = nullptr;
    if (!s2) {
        cudaStreamCreateWithFlags(&s2, cudaStreamNonBlocking);
        cudaEventCreateWithFlags(&evFork, cudaEventDisableTiming);
        cudaEventCreateWithFlags(&evJoin, cudaEventDisableTiming);
    }

    const int gm = (N_NODES + 127) / 128;
    const int agg_blocks = (N_NODES * 32 + 255) / 256;

    // --- fork ---
    cudaEventRecord(evFork, 0);
    cudaStreamWaitEvent(s2, evFork, 0);

    // Keep GEMM1 at kernel-launch index 3 (ncu -s 5 lands there).
    k_detect<<<1, 32, 0, s2>>>((const int*)ei);                      // 0
    k_zero_deg<<<(N_NODES + 255) / 256, 256, 0, s2>>>();             // 1
    k_wt<<<(IN_DIM * HID + 255) / 256, 256>>>(W1, wt1, IN_DIM, HID); // 2 (s0)

    // --- GEMM1 (A fp32 = X) on stream 0, fp16 output ---             3 (s0)
    k_gemm_h<HID, false, false, false, false, true><<<gm, 256>>>(
        x, wt1, nullptr, nullptr, h16, N_NODES, IN_DIM);

    // --- rest of CSR prologue + weight converts on s2 ---
    k_convert_count<<<(N_EDGES + 255) / 256, 256, 0, s2>>>(ei);
    k_scan_sum<<<N_CHUNKS, SCAN_CHUNK, 0, s2>>>();
    k_scan_top<<<1, SCAN_CHUNK, 0, s2>>>();
    k_scan_fin<<<N_CHUNKS, SCAN_CHUNK, 0, s2>>>();
    k_bucket<<<(N_EDGES + 255) / 256, 256, 0, s2>>>();
    k_wt<<<(HID * HID + 255) / 256, 256, 0, s2>>>(W2,  wt2,  HID, HID);
    k_wt<<<(HID * HID + 255) / 256, 256, 0, s2>>>(Wf1, wtf1, HID, HID);
    k_wt<<<(HID * OUT_DIM + 255) / 256, 256, 0, s2>>>(Wf2, wtf2, HID, OUT_DIM);
    cudaEventRecord(evJoin, s2);

    // --- join: aggregation needs CSR (s2) + h16 (s0) ---
    cudaStreamWaitEvent(0, evJoin, 0);
    k_aggregate<<<agg_blocks, 256>>>(csr_src, rowstart, degi, h16, dinv, agg16);

    // --- layer 2: A = agg16 (fp16), PRE relu(a+b1) ---
    k_gemm_h<HID, true, true, false, false, true><<<gm, 256>>>(
        agg16, wt2, b1, nullptr, h16, N_NODES, HID);
    k_aggregate<<<agg_blocks, 256>>>(csr_src, rowstart, degi, h16, dinv, agg16);

    // --- MLP head: GEMM3 fp16 out, GEMM4 fp32 out ---
    k_gemm_h<HID, true, true, true, true, true><<<gm, 256>>>(
        agg16, wtf1, b2, bf1, h16, N_NODES, HID);
    k_gemm_h<OUT_DIM, true, false, true, false, false><<<gm, 256>>>(
        h16, wtf2, nullptr, bf2, out, N_NODES, HID);
}

// round 13
// speedup vs baseline: 1.1901x; 1.0071x over previous
#include <cuda_runtime.h>
#include <cuda_fp16.h>
#include <cstdint>

#define N_NODES 100000
#define N_EDGES 1600000
#define IN_DIM  256
#define HID     128
#define OUT_DIM 64

#define SCAN_CHUNK 1024
#define N_CHUNKS   ((N_NODES + SCAN_CHUNK - 1) / SCAN_CHUNK)   // 98

// Scratch (static device allocations — no cudaMalloc allowed)
__device__ __half g_h16[(size_t)N_NODES * HID];    // GEMM outputs (fp16)
__device__ __half g_agg16[(size_t)N_NODES * HID];  // aggregation outputs (fp16)
__device__ float  g_dinv[N_NODES];
__device__ int    g_src[N_EDGES];
__device__ int    g_dst[N_EDGES];
__device__ int    g_degi[N_NODES];
__device__ int    g_rowstart[N_NODES];
__device__ int    g_cursor[N_NODES];
__device__ int    g_csr_src[N_EDGES];
__device__ int    g_bsum[N_CHUNKS];
__device__ int    g_is64;

// fp16 transposed weights: Wt[n][k]
__device__ __half g_wt1[HID * IN_DIM];
__device__ __half g_wt2[HID * HID];
__device__ __half g_wtf1[HID * HID];
__device__ __half g_wtf2[OUT_DIM * HID];

// ======================= edge prologue =====================================
__global__ void k_detect(const int* __restrict__ ei32) {
    if (threadIdx.x == 0 && blockIdx.x == 0) {
        int all0 = 1;
        for (int i = 0; i < 256; i++)
            if (ei32[2 * i + 1] != 0) { all0 = 0; break; }
        g_is64 = all0;
    }
}

__global__ void k_zero_deg() {
    int i = blockIdx.x * blockDim.x + threadIdx.x;
    if (i < N_NODES) g_degi[i] = 0;
}

__global__ void k_convert_count(const void* __restrict__ ei) {
    int e = blockIdx.x * blockDim.x + threadIdx.x;
    if (e >= N_EDGES) return;
    int s, d;
    if (g_is64) {
        const long long* p = (const long long*)ei;
        s = (int)p[e];
        d = (int)p[e + N_EDGES];
    } else {
        const int* p = (const int*)ei;
        s = p[e];
        d = p[e + N_EDGES];
    }
    s = min(max(s, 0), N_NODES - 1);
    d = min(max(d, 0), N_NODES - 1);
    g_src[e] = s;
    g_dst[e] = d;
    atomicAdd(&g_degi[d], 1);
}

__global__ void k_scan_sum() {
    __shared__ int sh[SCAN_CHUNK];
    int i = blockIdx.x * SCAN_CHUNK + threadIdx.x;
    sh[threadIdx.x] = (i < N_NODES) ? g_degi[i] : 0;
    __syncthreads();
    for (int off = SCAN_CHUNK / 2; off > 0; off >>= 1) {
        if (threadIdx.x < off) sh[threadIdx.x] += sh[threadIdx.x + off];
        __syncthreads();
    }
    if (threadIdx.x == 0) g_bsum[blockIdx.x] = sh[0];
}

__global__ void k_scan_top() {
    __shared__ int sh[N_CHUNKS];
    if (threadIdx.x < N_CHUNKS) sh[threadIdx.x] = g_bsum[threadIdx.x];
    __syncthreads();
    if (threadIdx.x == 0) {
        int run = 0;
        for (int i = 0; i < N_CHUNKS; i++) { int v = sh[i]; sh[i] = run; run += v; }
    }
    __syncthreads();
    if (threadIdx.x < N_CHUNKS) g_bsum[threadIdx.x] = sh[threadIdx.x];
}

__global__ void k_scan_fin() {
    __shared__ int sh[SCAN_CHUNK];
    int i = blockIdx.x * SCAN_CHUNK + threadIdx.x;
    int v = (i < N_NODES) ? g_degi[i] : 0;
    sh[threadIdx.x] = v;
    __syncthreads();
    for (int off = 1; off < SCAN_CHUNK; off <<= 1) {
        int t = (threadIdx.x >= off) ? sh[threadIdx.x - off] : 0;
        __syncthreads();
        sh[threadIdx.x] += t;
        __syncthreads();
    }
    if (i < N_NODES) {
        int excl = g_bsum[blockIdx.x] + sh[threadIdx.x] - v;
        g_rowstart[i] = excl;
        g_cursor[i]   = excl;
        g_dinv[i]     = rsqrtf(1.0f + (float)g_degi[i]);
    }
}

__global__ void k_bucket() {
    int e = blockIdx.x * blockDim.x + threadIdx.x;
    if (e >= N_EDGES) return;
    int d = g_dst[e];
    int p = atomicAdd(&g_cursor[d], 1);
    g_csr_src[p] = g_src[e];
}

// ================= weight transpose+convert: W[K][N] -> Wt[n][k] fp16 ======
__global__ void k_wt(const float* __restrict__ W, __half* __restrict__ Wt,
                     int K, int N) {
    int idx = blockIdx.x * blockDim.x + threadIdx.x;
    if (idx >= K * N) return;
    int n = idx / K;
    int k = idx - n * K;
    Wt[(size_t)n * K + k] = __float2half(W[(size_t)k * N + n]);
}

// ============================ mma helper ===================================
__device__ __forceinline__ void mma_fp16(float d[4], const unsigned a[4], const unsigned b[2]) {
    asm volatile(
        "mma.sync.aligned.m16n8k16.row.col.f32.f16.f16.f32 "
        "{%0,%1,%2,%3}, {%4,%5,%6,%7}, {%8,%9}, {%0,%1,%2,%3};"
        : "+f"(d[0]), "+f"(d[1]), "+f"(d[2]), "+f"(d[3])
        : "r"(a[0]), "r"(a[1]), "r"(a[2]), "r"(a[3]), "r"(b[0]), "r"(b[1]));
}

// ============ GEMM1: fp32 A, BK=64 loop (R12 known-good geometry) ==========
// C[M,128] = A[M,K] @ Wt^T, fp16 output. No PRE/EPI.
__global__ void __launch_bounds__(256)
k_gemm_f32(const float* __restrict__ A, const __half* __restrict__ Wt,
           __half* __restrict__ C, int M, int K)
{
    constexpr int BN = 128, BM = 128, BK = 64;
    constexpr int WN = BN / 2;
    constexpr int NT = WN / 8;
    constexpr int RS = 36;

    __shared__ uint32_t As[BM * RS];
    __shared__ uint32_t Bs[BN * RS];

    const int tid  = threadIdx.x;
    const int wid  = tid >> 5;
    const int lane = tid & 31;
    const int wm   = wid & 3;
    const int wn   = wid >> 2;
    const int bm   = blockIdx.x * BM;
    const int lq   = lane & 3;
    const int lr   = lane >> 2;

    float acc[2][NT][4];
#pragma unroll
    for (int tm = 0; tm < 2; tm++)
#pragma unroll
        for (int tn = 0; tn < NT; tn++)
#pragma unroll
            for (int i = 0; i < 4; i++) acc[tm][tn][i] = 0.0f;

    for (int k0 = 0; k0 < K; k0 += BK) {
#pragma unroll
        for (int p = 0; p < 8; p++) {
            int idx = p * 256 + tid;
            int r   = idx >> 4;
            int f4  = idx & 15;
            float4 v = make_float4(0.f, 0.f, 0.f, 0.f);
            if (bm + r < M)
                v = *(const float4*)&A[(size_t)(bm + r) * K + k0 + f4 * 4];
            __half2 h01 = __floats2half2_rn(v.x, v.y);
            __half2 h23 = __floats2half2_rn(v.z, v.w);
            As[r * RS + f4 * 2]     = *(uint32_t*)&h01;
            As[r * RS + f4 * 2 + 1] = *(uint32_t*)&h23;
        }
#pragma unroll
        for (int p = 0; p < 4; p++) {
            int idx = p * 256 + tid;
            int n   = idx >> 3;
            int u   = idx & 7;
            uint4 v = *(const uint4*)(Wt + (size_t)n * K + k0 + u * 8);
            *(uint4*)&Bs[n * RS + u * 4] = v;
        }
        __syncthreads();

#pragma unroll
        for (int ks = 0; ks < 4; ks++) {
            const int kp = ks * 8;
            unsigned af[2][4];
            unsigned bf[NT][2];
#pragma unroll
            for (int tm = 0; tm < 2; tm++) {
                int r = wm * 32 + tm * 16 + lr;
                af[tm][0] = As[r * RS + kp + lq];
                af[tm][1] = As[(r + 8) * RS + kp + lq];
                af[tm][2] = As[r * RS + kp + lq + 4];
                af[tm][3] = As[(r + 8) * RS + kp + lq + 4];
            }
#pragma unroll
            for (int tn = 0; tn < NT; tn++) {
                int c = wn * WN + tn * 8 + lr;
                bf[tn][0] = Bs[c * RS + kp + lq];
                bf[tn][1] = Bs[c * RS + kp + lq + 4];
            }
#pragma unroll
            for (int tm = 0; tm < 2; tm++)
#pragma unroll
                for (int tn = 0; tn < NT; tn++)
                    mma_fp16(acc[tm][tn], af[tm], bf[tn]);
        }
        __syncthreads();
    }

#pragma unroll
    for (int tm = 0; tm < 2; tm++) {
        int r0 = bm + wm * 32 + tm * 16 + lr;
#pragma unroll
        for (int half = 0; half < 2; half++) {
            int r = r0 + half * 8;
            if (r >= M) continue;
#pragma unroll
            for (int tn = 0; tn < NT; tn++) {
                int c = wn * WN + tn * 8 + lq * 2;
                __half2 hv = __floats2half2_rn(acc[tm][tn][half * 2 + 0],
                                               acc[tm][tn][half * 2 + 1]);
                *(__half2*)(C + (size_t)r * BN + c) = hv;
            }
        }
    }
}

// ========= GEMMs 2-4: fp16 A, K=128 single-shot (no k-loop) ================
// C[M,BN] = A16[M,128] @ Wt^T.  16 uint4 loads/thread front-batched,
// ONE __syncthreads, 8 mma k-steps, epilogue.
template <int BN, bool EPI_BIAS, bool EPI_RELU, bool HALF_OUT>
__global__ void __launch_bounds__(256)
k_gemm_hh(const __half* __restrict__ A16, const __half* __restrict__ Wt,
          const float* __restrict__ epiB, void* __restrict__ Cv, int M)
{
    constexpr int K = 128, BM = 128;
    constexpr int WN = BN / 2;
    constexpr int NT = WN / 8;
    constexpr int RS = 68;                  // 64 kpairs + 4 pad (≡4 mod 32)

    __shared__ uint32_t As[BM * RS];
    __shared__ uint32_t Bs[BN * RS];

    const int tid  = threadIdx.x;
    const int wid  = tid >> 5;
    const int lane = tid & 31;
    const int wm   = wid & 3;
    const int wn   = wid >> 2;
    const int bm   = blockIdx.x * BM;
    const int lq   = lane & 3;
    const int lr   = lane >> 2;

    // ---- A tile [128 x 128] fp16: 8 uint4 per thread ----
#pragma unroll
    for (int p = 0; p < 8; p++) {
        int idx = p * 256 + tid;
        int r   = idx >> 4;
        int u   = idx & 15;
        uint4 v = make_uint4(0u, 0u, 0u, 0u);
        if (bm + r < M)
            v = *(const uint4*)(A16 + (size_t)(bm + r) * K + u * 8);
        *(uint4*)&As[r * RS + u * 4] = v;
    }
    // ---- B tile [BN x 128] fp16 ----
    constexpr int BU = BN * 16;
#pragma unroll
    for (int p = 0; p < BU / 256; p++) {
        int idx = p * 256 + tid;
        int n   = idx >> 4;
        int u   = idx & 15;
        uint4 v = *(const uint4*)(Wt + (size_t)n * K + u * 8);
        *(uint4*)&Bs[n * RS + u * 4] = v;
    }
    __syncthreads();

    float acc[2][NT][4];
#pragma unroll
    for (int tm = 0; tm < 2; tm++)
#pragma unroll
        for (int tn = 0; tn < NT; tn++)
#pragma unroll
            for (int i = 0; i < 4; i++) acc[tm][tn][i] = 0.0f;

#pragma unroll
    for (int ks = 0; ks < 8; ks++) {
        const int kp = ks * 8;
        unsigned af[2][4];
        unsigned bf[NT][2];
#pragma unroll
        for (int tm = 0; tm < 2; tm++) {
            int r = wm * 32 + tm * 16 + lr;
            af[tm][0] = As[r * RS + kp + lq];
            af[tm][1] = As[(r + 8) * RS + kp + lq];
            af[tm][2] = As[r * RS + kp + lq + 4];
            af[tm][3] = As[(r + 8) * RS + kp + lq + 4];
        }
#pragma unroll
        for (int tn = 0; tn < NT; tn++) {
            int c = wn * WN + tn * 8 + lr;
            bf[tn][0] = Bs[c * RS + kp + lq];
            bf[tn][1] = Bs[c * RS + kp + lq + 4];
        }
#pragma unroll
        for (int tm = 0; tm < 2; tm++)
#pragma unroll
            for (int tn = 0; tn < NT; tn++)
                mma_fp16(acc[tm][tn], af[tm], bf[tn]);
    }

    // ---- epilogue ----
#pragma unroll
    for (int tm = 0; tm < 2; tm++) {
        int r0 = bm + wm * 32 + tm * 16 + lr;
#pragma unroll
        for (int half = 0; half < 2; half++) {
            int r = r0 + half * 8;
            if (r >= M) continue;
#pragma unroll
            for (int tn = 0; tn < NT; tn++) {
                int c = wn * WN + tn * 8 + lq * 2;
                float v0 = acc[tm][tn][half * 2 + 0];
                float v1 = acc[tm][tn][half * 2 + 1];
                if (EPI_BIAS) { v0 += epiB[c]; v1 += epiB[c + 1]; }
                if (EPI_RELU) { v0 = fmaxf(v0, 0.f); v1 = fmaxf(v1, 0.f); }
                if (HALF_OUT) {
                    __half2 hv = __floats2half2_rn(v0, v1);
                    *(__half2*)((__half*)Cv + (size_t)r * BN + c) = hv;
                } else {
                    float* C = (float*)Cv;
                    C[(size_t)r * BN + c]     = v0;
                    C[(size_t)r * BN + c + 1] = v1;
                }
            }
        }
    }
}

// ====== gather aggregation: fp16 in, fp16 out, optional fused bias+relu ====
__device__ __forceinline__ void h16_load4(const __half* base, size_t row,
                                          int lane, float f[4]) {
    uint2 u = *(const uint2*)(base + row * HID + lane * 4);
    __half2 p0 = *(__half2*)&u.x;
    __half2 p1 = *(__half2*)&u.y;
    float2 a = __half22float2(p0);
    float2 b = __half22float2(p1);
    f[0] = a.x; f[1] = a.y; f[2] = b.x; f[3] = b.y;
}

template <bool BIAS_RELU>
__global__ void __launch_bounds__(256)
k_aggregate(const int* __restrict__ csr_src,
            const int* __restrict__ rowstart,
            const int* __restrict__ degi,
            const __half* __restrict__ h16,
            const float* __restrict__ dinv,
            const float* __restrict__ bias,
            __half* __restrict__ agg16)
{
    int n    = (blockIdx.x * blockDim.x + threadIdx.x) >> 5;
    int lane = threadIdx.x & 31;
    if (n >= N_NODES) return;

    float di = dinv[n];
    float f[4];
    h16_load4(h16, (size_t)n, lane, f);
    float s0 = di * di;
    float4 acc = make_float4(f[0] * s0, f[1] * s0, f[2] * s0, f[3] * s0);

    int beg = rowstart[n];
    int cnt = degi[n];
    int j = 0;
    for (; j + 2 <= cnt; j += 2) {
        int sa = csr_src[beg + j];
        int sb = csr_src[beg + j + 1];
        float na = dinv[sa] * di;
        float nb = dinv[sb] * di;
        float fa[4], fb[4];
        h16_load4(h16, (size_t)sa, lane, fa);
        h16_load4(h16, (size_t)sb, lane, fb);
        acc.x = fmaf(fa[0], na, acc.x); acc.y = fmaf(fa[1], na, acc.y);
        acc.z = fmaf(fa[2], na, acc.z); acc.w = fmaf(fa[3], na, acc.w);
        acc.x = fmaf(fb[0], nb, acc.x); acc.y = fmaf(fb[1], nb, acc.y);
        acc.z = fmaf(fb[2], nb, acc.z); acc.w = fmaf(fb[3], nb, acc.w);
    }
    if (j < cnt) {
        int sa = csr_src[beg + j];
        float na = dinv[sa] * di;
        float fa[4];
        h16_load4(h16, (size_t)sa, lane, fa);
        acc.x = fmaf(fa[0], na, acc.x); acc.y = fmaf(fa[1], na, acc.y);
        acc.z = fmaf(fa[2], na, acc.z); acc.w = fmaf(fa[3], na, acc.w);
    }

    if (BIAS_RELU) {
        int c = lane * 4;
        acc.x = fmaxf(acc.x + bias[c + 0], 0.f);
        acc.y = fmaxf(acc.y + bias[c + 1], 0.f);
        acc.z = fmaxf(acc.z + bias[c + 2], 0.f);
        acc.w = fmaxf(acc.w + bias[c + 3], 0.f);
    }
    __half2 o0 = __floats2half2_rn(acc.x, acc.y);
    __half2 o1 = __floats2half2_rn(acc.z, acc.w);
    uint2 u;
    u.x = *(uint32_t*)&o0;
    u.y = *(uint32_t*)&o1;
    *(uint2*)(agg16 + (size_t)n * HID + lane * 4) = u;
}

// ---------------------------------------------------------------------------
extern "C" void kernel_launch(void* const* d_in, const int* in_sizes, int n_in,
                              void* d_out, int out_size)
{
    const float* x   = (const float*)d_in[0];
    const void*  ei  = d_in[1];
    const float* W1  = (const float*)d_in[2];
    const float* b1  = (const float*)d_in[3];
    const float* W2  = (const float*)d_in[4];
    const float* b2  = (const float*)d_in[5];
    const float* Wf1 = (const float*)d_in[6];
    const float* bf1 = (const float*)d_in[7];
    const float* Wf2 = (const float*)d_in[8];
    const float* bf2 = (const float*)d_in[9];
    float* out = (float*)d_out;

    float *dinv;
    __half *h16, *agg16, *wt1, *wt2, *wtf1, *wtf2;
    int *csr_src, *rowstart, *degi;
    cudaGetSymbolAddress((void**)&h16,      g_h16);
    cudaGetSymbolAddress((void**)&agg16,    g_agg16);
    cudaGetSymbolAddress((void**)&dinv,     g_dinv);
    cudaGetSymbolAddress((void**)&csr_src,  g_csr_src);
    cudaGetSymbolAddress((void**)&rowstart, g_rowstart);
    cudaGetSymbolAddress((void**)&degi,     g_degi);
    cudaGetSymbolAddress((void**)&wt1,      g_wt1);
    cudaGetSymbolAddress((void**)&wt2,      g_wt2);
    cudaGetSymbolAddress((void**)&wtf1,     g_wtf1);
    cudaGetSymbolAddress((void**)&wtf2,     g_wtf2);

    static cudaStream_t s2 = nullptr;
    static cudaEvent_t evFork = nullptr, evJoin = nullptr;
    if (!s2) {
        cudaStreamCreateWithFlags(&s2, cudaStreamNonBlocking);
        cudaEventCreateWithFlags(&evFork, cudaEventDisableTiming);
        cudaEventCreateWithFlags(&evJoin, cudaEventDisableTiming);
    }

    const int gm = (N_NODES + 127) / 128;
    const int agg_blocks = (N_NODES * 32 + 255) / 256;

    // --- fork ---
    cudaEventRecord(evFork, 0);
    cudaStreamWaitEvent(s2, evFork, 0);

    // Keep GEMM1 at kernel-launch index 3 (ncu -s 5 lands there).
    k_detect<<<1, 32, 0, s2>>>((const int*)ei);                      // 0
    k_zero_deg<<<(N_NODES + 255) / 256, 256, 0, s2>>>();             // 1
    k_wt<<<(IN_DIM * HID + 255) / 256, 256>>>(W1, wt1, IN_DIM, HID); // 2 (s0)

    // --- GEMM1 (A fp32 = X) on stream 0, fp16 output ---             3 (s0)
    k_gemm_f32<<<gm, 256>>>(x, wt1, h16, N_NODES, IN_DIM);

    // --- rest of CSR prologue + weight converts on s2 ---
    k_convert_count<<<(N_EDGES + 255) / 256, 256, 0, s2>>>(ei);
    k_scan_sum<<<N_CHUNKS, SCAN_CHUNK, 0, s2>>>();
    k_scan_top<<<1, SCAN_CHUNK, 0, s2>>>();
    k_scan_fin<<<N_CHUNKS, SCAN_CHUNK, 0, s2>>>();
    k_bucket<<<(N_EDGES + 255) / 256, 256, 0, s2>>>();
    k_wt<<<(HID * HID + 255) / 256, 256, 0, s2>>>(W2,  wt2,  HID, HID);
    k_wt<<<(HID * HID + 255) / 256, 256, 0, s2>>>(Wf1, wtf1, HID, HID);
    k_wt<<<(HID * OUT_DIM + 255) / 256, 256, 0, s2>>>(Wf2, wtf2, HID, OUT_DIM);
    cudaEventRecord(evJoin, s2);

    // --- join: aggregation needs CSR (s2) + h16 (s0) ---
    cudaStreamWaitEvent(0, evJoin, 0);
    // agg1 = relu(aggregate(h16) + b1)   (bias+relu folded)
    k_aggregate<true><<<agg_blocks, 256>>>(csr_src, rowstart, degi, h16, dinv, b1, agg16);

    // --- layer 2: GEMM2 (no PRE), then agg2 = relu(aggregate + b2) ---
    k_gemm_hh<HID, false, false, true><<<gm, 256>>>(agg16, wt2, nullptr, h16, N_NODES);
    k_aggregate<true><<<agg_blocks, 256>>>(csr_src, rowstart, degi, h16, dinv, b2, agg16);

    // --- MLP head: GEMM3 (EPI bf1+relu, fp16 out), GEMM4 (EPI bf2, fp32) ---
    k_gemm_hh<HID, true, true, true><<<gm, 256>>>(agg16, wtf1, bf1, h16, N_NODES);
    k_gemm_hh<OUT_DIM, true, false, false><<<gm, 256>>>(h16, wtf2, bf2, out, N_NODES);
}